// round 1
// baseline (speedup 1.0000x reference)
#include <cuda_runtime.h>
#include <stdint.h>
#include <float.h>

// Problem shape (fixed by the dataset):
//   data: [64, 1024, 256] f32, locs: [64, 256, 2] f32
//   out:  [64, 1024, 50, 50] f32  (flat [64,1024,2500])
#define B_  64
#define T_  1024
#define N_  256
#define G_  50
#define GG  2500          // G_*G_
#define TPB 256
#define T_PER_BLOCK 32    // t-rows per gather block

// Scratch: nearest sensor index per (batch, grid cell). Indices fit in uint8.
// 64*2500 = 160000 bytes. Device global => no allocation in kernel_launch.
__device__ uint8_t g_nearest[B_ * GG];

// ---------------------------------------------------------------------------
// Kernel A: per-cell argmin over 256 sensors.
// Reproduces jnp.argmin(sqrt(dx^2+dy^2)) exactly:
//   - no FMA contraction (mul/add with explicit rn intrinsics)
//   - sqrt evaluated lazily only on running-min updates of d^2 (IEEE __fsqrt_rn),
//     with strict-less index update => first-index-wins on fp32 sqrt ties,
//     identical to jnp.argmin semantics.
// ---------------------------------------------------------------------------
__global__ void nearest_kernel(const float* __restrict__ locs) {
    __shared__ float2 sloc[N_];
    const int b = blockIdx.y;
    const int tid = threadIdx.x;

    // load + transform this batch's sensor locations: l*25 + 25 (mul then add, rn)
    {
        float2 l = reinterpret_cast<const float2*>(locs)[b * N_ + tid];
        sloc[tid].x = __fadd_rn(__fmul_rn(l.x, 25.0f), 25.0f);
        sloc[tid].y = __fadd_rn(__fmul_rn(l.y, 25.0f), 25.0f);
    }
    __syncthreads();

    const int g = blockIdx.x * blockDim.x + tid;
    if (g >= GG) return;

    const float gx = (float)(g / G_);   // mgrid row index
    const float gy = (float)(g % G_);   // mgrid col index

    float bsq = FLT_MAX;   // best squared distance (tightened even on sqrt ties)
    float bs  = FLT_MAX;   // best sqrt distance (what the reference compares)
    int   bi  = 0;

    #pragma unroll 4
    for (int j = 0; j < N_; ++j) {
        float dx = __fsub_rn(sloc[j].x, gx);
        float dy = __fsub_rn(sloc[j].y, gy);
        float d2 = __fadd_rn(__fmul_rn(dx, dx), __fmul_rn(dy, dy));
        if (d2 < bsq) {                 // necessary condition for s < bs (monotone)
            bsq = d2;
            float s = __fsqrt_rn(d2);   // rare: ~H_256 ≈ 6 evals per cell
            if (s < bs) { bs = s; bi = j; }   // strict-less => first index wins ties
        }
    }
    g_nearest[b * GG + g] = (uint8_t)bi;
}

// ---------------------------------------------------------------------------
// Kernel B: gather/broadcast.  out[b,t,g] = data[b,t, nearest[b,g]]
// One block = (batch b, 32 consecutive t-rows).
//   - nearest[b,:] (2500 B) loaded once, held in 12 registers/thread
//   - each 1 KB data row staged in smem
//   - 625 coalesced float4 stores per row (2500 % 4 == 0, base aligned)
// ---------------------------------------------------------------------------
__global__ __launch_bounds__(TPB)
void gather_kernel(const float* __restrict__ data, float* __restrict__ out) {
    __shared__ float   row[N_];
    __shared__ uint8_t sidx[GG];        // 2500 bytes; 2500 % 4 == 0

    const int b   = blockIdx.y;
    const int tid = threadIdx.x;

    // stage indices for this batch (uint32 loads: 625 words)
    {
        const uint32_t* src = reinterpret_cast<const uint32_t*>(g_nearest + (size_t)b * GG);
        uint32_t* dst = reinterpret_cast<uint32_t*>(sidx);
        #pragma unroll
        for (int k = tid; k < GG / 4; k += TPB) dst[k] = src[k];
    }
    __syncthreads();

    // pull this thread's gather indices into registers (up to 3 float4 groups)
    int idx[3][4];
    #pragma unroll
    for (int gi = 0; gi < 3; ++gi) {
        int k = tid + gi * TPB;
        if (k < GG / 4) {
            idx[gi][0] = sidx[4 * k + 0];
            idx[gi][1] = sidx[4 * k + 1];
            idx[gi][2] = sidx[4 * k + 2];
            idx[gi][3] = sidx[4 * k + 3];
        }
    }

    const int t0 = blockIdx.x * T_PER_BLOCK;
    const float* drow = data + ((size_t)b * T_ + t0) * N_;
    float*       orow = out  + ((size_t)b * T_ + t0) * GG;

    for (int tt = 0; tt < T_PER_BLOCK; ++tt) {
        __syncthreads();                 // protect row[] reuse across iterations
        row[tid] = drow[tid];            // coalesced 1 KB row load
        __syncthreads();

        float4* o4 = reinterpret_cast<float4*>(orow);
        #pragma unroll
        for (int gi = 0; gi < 3; ++gi) {
            int k = tid + gi * TPB;
            if (k < GG / 4) {
                float4 v;
                v.x = row[idx[gi][0]];
                v.y = row[idx[gi][1]];
                v.z = row[idx[gi][2]];
                v.w = row[idx[gi][3]];
                o4[k] = v;               // coalesced STG.128
            }
        }
        drow += N_;
        orow += GG;
    }
}

// ---------------------------------------------------------------------------
extern "C" void kernel_launch(void* const* d_in, const int* in_sizes, int n_in,
                              void* d_out, int out_size) {
    // identify inputs by element count (data: 16,777,216; locs: 32,768)
    const float* data = (const float*)d_in[0];
    const float* locs = (const float*)d_in[1];
    if (n_in >= 2 && in_sizes[0] < in_sizes[1]) {
        data = (const float*)d_in[1];
        locs = (const float*)d_in[0];
    }
    float* out = (float*)d_out;

    dim3 gridA((GG + TPB - 1) / TPB, B_);     // 10 x 64 blocks
    nearest_kernel<<<gridA, TPB>>>(locs);

    dim3 gridB(T_ / T_PER_BLOCK, B_);         // 32 x 64 blocks
    gather_kernel<<<gridB, TPB>>>(data, out);
}

// round 2
// speedup vs baseline: 1.0021x; 1.0021x over previous
#include <cuda_runtime.h>
#include <stdint.h>
#include <float.h>

// Problem shape (fixed by the dataset):
//   data: [64, 1024, 256] f32, locs: [64, 256, 2] f32
//   out:  [64, 1024, 50, 50] f32  (flat [64,1024,2500])
#define B_  64
#define T_  1024
#define N_  256
#define G_  50
#define GG  2500          // G_*G_
#define TPB 256
#define T_PER_BLOCK 32    // t-rows per gather block
#define R_  4             // t-rows staged per barrier window
#define NCHAIN 4          // independent argmin chains in nearest_kernel

// Scratch: nearest sensor index per (batch, grid cell). Indices fit in uint8.
__device__ uint8_t g_nearest[B_ * GG];

// ---------------------------------------------------------------------------
// Kernel A: per-cell argmin over 256 sensors.
// Exact reproduction of jnp.argmin(sqrt(dx^2+dy^2)):
//   - explicit rn mul/add (no FMA contraction, matches XLA rounding)
//   - sqrt evaluated lazily only on running-min updates of d^2; strict-less
//     update => first-index-wins ties, same as jnp.argmin.
// 4 independent chains (blocked j-partition, interleaved execution) break the
// serial compare-latency chain; ordered merge preserves first-wins.
// ---------------------------------------------------------------------------
__global__ void nearest_kernel(const float* __restrict__ locs) {
    __shared__ float2 sloc[N_];
    const int b = blockIdx.y;
    const int tid = threadIdx.x;

    {
        float2 l = reinterpret_cast<const float2*>(locs)[b * N_ + tid];
        sloc[tid].x = __fadd_rn(__fmul_rn(l.x, 25.0f), 25.0f);
        sloc[tid].y = __fadd_rn(__fmul_rn(l.y, 25.0f), 25.0f);
    }
    __syncthreads();

    const int g = blockIdx.x * blockDim.x + tid;
    if (g >= GG) return;

    const float gx = (float)(g / G_);
    const float gy = (float)(g % G_);

    float bsq[NCHAIN], bs[NCHAIN];
    int   bi[NCHAIN];
    #pragma unroll
    for (int c = 0; c < NCHAIN; ++c) { bsq[c] = FLT_MAX; bs[c] = FLT_MAX; bi[c] = 0; }

    const int L = N_ / NCHAIN;   // 64 iterations, 4 independent updates each
    #pragma unroll 4
    for (int i = 0; i < L; ++i) {
        #pragma unroll
        for (int c = 0; c < NCHAIN; ++c) {
            int j = c * L + i;                 // chain c owns contiguous block
            float dx = __fsub_rn(sloc[j].x, gx);
            float dy = __fsub_rn(sloc[j].y, gy);
            float d2 = __fadd_rn(__fmul_rn(dx, dx), __fmul_rn(dy, dy));
            if (d2 < bsq[c]) {
                bsq[c] = d2;
                float s = __fsqrt_rn(d2);      // rare (~6x per chain total)
                if (s < bs[c]) { bs[c] = s; bi[c] = j; }
            }
        }
    }
    // ordered merge: chain 0 has smallest j's; strict < keeps first-index-wins
    float best = bs[0]; int besti = bi[0];
    #pragma unroll
    for (int c = 1; c < NCHAIN; ++c)
        if (bs[c] < best) { best = bs[c]; besti = bi[c]; }

    g_nearest[b * GG + g] = (uint8_t)besti;
}

// ---------------------------------------------------------------------------
// Kernel B: gather/broadcast.  out[b,t,g] = data[b,t, nearest[b,g]]
// Transposed row cache: rows4[sensor] = float4 of 4 consecutive t-values.
// One LDS.128 per sensor lookup serves 4 output rows; register transpose
// then 4 coalesced STG.128. 4x fewer LDS instr + 4x fewer barriers than
// the scalar version.
// ---------------------------------------------------------------------------
__global__ __launch_bounds__(TPB)
void gather_kernel(const float* __restrict__ data, float* __restrict__ out) {
    __shared__ float4  rows4[N_];     // [sensor] -> values for 4 t-rows
    __shared__ uint8_t sidx[GG];      // 2500 bytes, 2500 % 4 == 0

    const int b   = blockIdx.y;
    const int tid = threadIdx.x;

    // stage this batch's indices (625 word loads, L2-resident after 1st block)
    {
        const uint32_t* src = reinterpret_cast<const uint32_t*>(g_nearest + (size_t)b * GG);
        uint32_t* dst = reinterpret_cast<uint32_t*>(sidx);
        #pragma unroll
        for (int k = tid; k < GG / 4; k += TPB) dst[k] = src[k];
    }
    __syncthreads();

    // this thread's gather indices in registers (3 groups of 4 grid cells)
    int idx[3][4];
    #pragma unroll
    for (int gi = 0; gi < 3; ++gi) {
        int k = tid + gi * TPB;
        if (k < GG / 4) {
            idx[gi][0] = sidx[4 * k + 0];
            idx[gi][1] = sidx[4 * k + 1];
            idx[gi][2] = sidx[4 * k + 2];
            idx[gi][3] = sidx[4 * k + 3];
        }
    }

    const int t0 = blockIdx.x * T_PER_BLOCK;
    const float* dbase = data + ((size_t)b * T_ + t0) * (size_t)N_;
    float*       obase = out  + ((size_t)b * T_ + t0) * (size_t)GG;

    #pragma unroll 1
    for (int c = 0; c < T_PER_BLOCK / R_; ++c) {
        __syncthreads();               // protect rows4 reuse
        // stage 4 rows transposed: thread tid owns sensor tid
        {
            const float* d0 = dbase + (size_t)(c * R_) * N_ + tid;
            float4 v;
            v.x = __ldcs(d0 + 0 * N_);   // coalesced, streaming
            v.y = __ldcs(d0 + 1 * N_);
            v.z = __ldcs(d0 + 2 * N_);
            v.w = __ldcs(d0 + 3 * N_);
            rows4[tid] = v;
        }
        __syncthreads();

        float* o = obase + (size_t)(c * R_) * GG;
        #pragma unroll
        for (int gi = 0; gi < 3; ++gi) {
            int k = tid + gi * TPB;
            if (k < GG / 4) {
                float4 s0 = rows4[idx[gi][0]];   // LDS.128: 4 t-values each
                float4 s1 = rows4[idx[gi][1]];
                float4 s2 = rows4[idx[gi][2]];
                float4 s3 = rows4[idx[gi][3]];
                // register transpose -> one float4 store per t-row
                __stcs(reinterpret_cast<float4*>(o + 0 * GG) + k,
                       make_float4(s0.x, s1.x, s2.x, s3.x));
                __stcs(reinterpret_cast<float4*>(o + 1 * GG) + k,
                       make_float4(s0.y, s1.y, s2.y, s3.y));
                __stcs(reinterpret_cast<float4*>(o + 2 * GG) + k,
                       make_float4(s0.z, s1.z, s2.z, s3.z));
                __stcs(reinterpret_cast<float4*>(o + 3 * GG) + k,
                       make_float4(s0.w, s1.w, s2.w, s3.w));
            }
        }
    }
}

// ---------------------------------------------------------------------------
extern "C" void kernel_launch(void* const* d_in, const int* in_sizes, int n_in,
                              void* d_out, int out_size) {
    const float* data = (const float*)d_in[0];
    const float* locs = (const float*)d_in[1];
    if (n_in >= 2 && in_sizes[0] < in_sizes[1]) {
        data = (const float*)d_in[1];
        locs = (const float*)d_in[0];
    }
    float* out = (float*)d_out;

    dim3 gridA((GG + TPB - 1) / TPB, B_);     // 10 x 64 blocks
    nearest_kernel<<<gridA, TPB>>>(locs);

    dim3 gridB(T_ / T_PER_BLOCK, B_);         // 32 x 64 blocks
    gather_kernel<<<gridB, TPB>>>(data, out);
}